// round 9
// baseline (speedup 1.0000x reference)
#include <cuda_runtime.h>

#define BB 8
#define NV 207
#define TT 12
#define LL 2
#define NGH 8
#define ALPHA 0.2f
#define NN (NV*NV)
#define ST 20   // k-major stride for activation buffers (floats)
#define PT 14   // stride for partial-sum buffers
#define XR 418  // xsa row stride (per t)
#define WTL 49152  // transposed-weights stride per layer

typedef unsigned long long u64t;

// scratch: gat output (B*N groups, layout per group: e*12+t)
__device__ float g_out[BB*NV*TT*64];
// transposed weights: per layer: WqT,WkT,WvT,WoT [64][64]; fw1T [256][64]; fw2T [64][256]
__device__ __align__(16) float g_wT[2*WTL];

__device__ __forceinline__ float warp_sum(float v){
  #pragma unroll
  for (int o=16;o;o>>=1) v += __shfl_xor_sync(0xffffffffu, v, o);
  return v;
}
__device__ __forceinline__ u64t pack2(float v){
  u64t r; asm("mov.b64 %0, {%1, %1};" : "=l"(r) : "f"(v)); return r;
}
__device__ __forceinline__ void fma2(u64t &acc, u64t a, u64t b){
  asm("fma.rn.f32x2 %0, %1, %2, %0;" : "+l"(acc) : "l"(a), "l"(b));
}

// ---------------------------------------------------------------------------
// K0: one-shot weight transpose into g_wT (column-major [col][k]).
// ---------------------------------------------------------------------------
__global__ void __launch_bounds__(256) k_tw(
    const float* __restrict__ Wq, const float* __restrict__ Wk,
    const float* __restrict__ Wv, const float* __restrict__ Wo,
    const float* __restrict__ fw1, const float* __restrict__ fw2)
{
  int idx = blockIdx.x*256 + threadIdx.x;
  if (idx >= 2*WTL) return;
  int l = idx / WTL, r = idx - l*WTL;
  float* dst = g_wT + l*WTL;
  if (r < 16384){
    int m = r >> 12, q = r & 4095;      // q = e*64 + k
    int e = q >> 6, k = q & 63;
    const float* src = (m==0?Wq:(m==1?Wk:(m==2?Wv:Wo))) + l*4096;
    dst[r] = src[k*64 + e];
  } else if (r < 32768){
    int q = r - 16384; int f = q >> 6, k = q & 63;   // q = f*64 + k
    dst[r] = fw1[l*16384 + k*256 + f];
  } else {
    int q = r - 32768; int e = q >> 8, k = q & 255;  // q = e*256 + k
    dst[r] = fw2[l*16384 + k*64 + e];
  }
}

// ---------------------------------------------------------------------------
// K1: GAT + conv1. Block = (b, 2-row chunk). x[b] staged TRANSPOSED [t][2n+c].
// ---------------------------------------------------------------------------
__global__ void __launch_bounds__(128) k_gat(
    const float* __restrict__ x,      // (B,C,N,T)
    const int*   __restrict__ adj,    // (B,N,N)
    const float* __restrict__ W2,     // (8,4,2)
    const float* __restrict__ ga,     // (8,2)
    const float* __restrict__ gb,     // (8,2)
    const float* __restrict__ w1,     // (4,64)
    const float* __restrict__ b1)     // (64)
{
  __shared__ float xsa[TT*XR];     // [t][2n+c]
  __shared__ int   adjs[2*NV];
  __shared__ float w1s[256];
  __shared__ float b1s[64];

  int b  = blockIdx.x;
  int i0 = blockIdx.y * 2;
  int tid = threadIdx.x;

  const float* xb = x + (long)b*2*NV*TT;
  for (int idx=tid; idx<2*NV*TT; idx+=128){
    int c = idx/(NV*TT); int r = idx - c*NV*TT;
    int n = r/TT, t = r - n*TT;
    xsa[t*XR + 2*n + c] = xb[idx];
  }
  int nrows = (NV - i0) < 2 ? (NV - i0) : 2;
  for (int idx=tid; idx<nrows*NV; idx+=128){
    int ii = idx / NV, j = idx - ii*NV;
    adjs[ii*NV+j] = adj[((long)b*NV + i0+ii)*NV + j];
  }
  for (int idx=tid; idx<256; idx+=128) w1s[idx]=w1[idx];
  if (tid<64) b1s[tid]=b1[tid];
  __syncthreads();

  int warp = tid>>5, lane = tid&31;

  for (int task = warp; task < 24; task += 4){
    int t  = task % 12;
    int ii = task / 12;
    int i  = i0 + ii;
    if (i >= NV) continue;
    const int* arow = adjs + ii*NV;
    const float* xrow = xsa + t*XR;

    float acc0=0.f, acc1=0.f;
    #pragma unroll
    for (int hg=0; hg<2; hg++){
      float w2r[4][4][2], ar[4][2];
      #pragma unroll
      for (int hh=0;hh<4;hh++){
        int h = hg*4+hh;
        #pragma unroll
        for (int k=0;k<4;k++){
          w2r[hh][k][0]=__ldg(W2+(h*4+k)*2+0);
          w2r[hh][k][1]=__ldg(W2+(h*4+k)*2+1);
        }
        ar[hh][0]=__ldg(ga+h*2); ar[hh][1]=__ldg(ga+h*2+1);
      }
      float d[4]={0,0,0,0}, n0[4]={0,0,0,0}, n1[4]={0,0,0,0};
      #pragma unroll
      for (int jj=0; jj<7; jj++){
        int j = jj*32 + lane;
        bool valid = j < NV;
        int jc = valid ? j : 0;
        bool ok = valid && (arow[jc] > 0);
        int r0 = 2*(i*NV + jc);
        int r1 = r0 + 1;
        int a0 = (r0 < NN) ? (r0 / NV) : ((r0 - NN) % NV);
        int a1 = (r1 < NN) ? (r1 / NV) : ((r1 - NN) % NV);
        float2 ca = *(const float2*)(xrow + 2*a0);
        float2 cb = *(const float2*)(xrow + 2*a1);
        float2 xj = *(const float2*)(xrow + 2*jc);
        #pragma unroll
        for (int hh=0;hh<4;hh++){
          float we0 = ca.x*w2r[hh][0][0] + ca.y*w2r[hh][1][0] + cb.x*w2r[hh][2][0] + cb.y*w2r[hh][3][0];
          float we1 = ca.x*w2r[hh][0][1] + ca.y*w2r[hh][1][1] + cb.x*w2r[hh][2][1] + cb.y*w2r[hh][3][1];
          we0 = (we0 > 0.f) ? we0 : ALPHA*we0;
          we1 = (we1 > 0.f) ? we1 : ALPHA*we1;
          float e = we0*ar[hh][0] + we1*ar[hh][1];
          float w = ok ? __expf(e) : 0.f;
          d[hh]  += w;
          n0[hh] += w*xj.x;
          n1[hh] += w*xj.y;
        }
      }
      #pragma unroll
      for (int off=16; off; off>>=1){
        #pragma unroll
        for (int hh=0;hh<4;hh++){
          d[hh]  += __shfl_xor_sync(0xffffffffu, d[hh],  off);
          n0[hh] += __shfl_xor_sync(0xffffffffu, n0[hh], off);
          n1[hh] += __shfl_xor_sync(0xffffffffu, n1[hh], off);
        }
      }
      #pragma unroll
      for (int hh=0;hh<4;hh++){
        int h = hg*4+hh;
        float inv = 1.0f/d[hh];
        float z0 = n0[hh]*inv + __ldg(gb+h*2+0);
        float z1 = n1[hh]*inv + __ldg(gb+h*2+1);
        acc0 += 1.f - __fdividef(2.f, __expf(2.f*z0)+1.f);
        acc1 += 1.f - __fdividef(2.f, __expf(2.f*z1)+1.f);
      }
    }
    acc0 *= 0.125f; acc1 *= 0.125f;

    float xi0 = xrow[2*i], xi1 = xrow[2*i+1];
    long obase = (long)(b*NV + i)*768;
    #pragma unroll
    for (int r=0;r<2;r++){
      int e = lane + r*32;
      g_out[obase + e*12 + t] = xi0*w1s[e] + xi1*w1s[64+e]
                              + acc0*w1s[128+e] + acc1*w1s[192+e] + b1s[e];
    }
  }
}

// ---------------------------------------------------------------------------
// 2-column GEMM with TRANSPOSED weights: one LDG.128 per column per 4 k.
// ---------------------------------------------------------------------------
#define SUBK(WX, WY, OFF) { \
    u64t wa_ = pack2(WX), wb_ = pack2(WY); \
    const ulonglong2* a_ = (const ulonglong2*)(arow + (OFF)*ST); \
    ulonglong2 v0 = a_[0], v1 = a_[1], v2 = a_[2]; \
    fma2(A[0], v0.x, wa_); fma2(Bc[0], v0.x, wb_); \
    fma2(A[1], v0.y, wa_); fma2(Bc[1], v0.y, wb_); \
    fma2(A[2], v1.x, wa_); fma2(Bc[2], v1.x, wb_); \
    fma2(A[3], v1.y, wa_); fma2(Bc[3], v1.y, wb_); \
    fma2(A[4], v2.x, wa_); fma2(Bc[4], v2.x, wb_); \
    fma2(A[5], v2.y, wa_); fma2(Bc[5], v2.y, wb_); }

__device__ __forceinline__ void gemm2T(const float* __restrict__ sIn,
                                       const float* __restrict__ WT, int ldk,
                                       int c0, int c1, int k0, int nk,
                                       u64t A[6], u64t Bc[6]){
  const float4* wa4 = (const float4*)(WT + c0*ldk + k0);
  const float4* wb4 = (const float4*)(WT + c1*ldk + k0);
  #pragma unroll 2
  for (int k4=0; k4<nk/4; k4++){
    float4 wa = __ldg(wa4 + k4);
    float4 wb = __ldg(wb4 + k4);
    const float* arow = sIn + (k0 + 4*k4)*ST;
    SUBK(wa.x, wb.x, 0)
    SUBK(wa.y, wb.y, 1)
    SUBK(wa.z, wb.z, 2)
    SUBK(wa.w, wb.w, 3)
  }
}

__device__ __forceinline__ void store6(float* dst, const u64t A[6]){
  #pragma unroll
  for (int p=0;p<6;p++) ((float2*)dst)[p] = *(const float2*)&A[p];
}

// ---------------------------------------------------------------------------
// K2: BOTH transformer layers + conv2/conv3 head fused.
// grid 1656 (=B*N), block 256. smem arena 46KB.
// ---------------------------------------------------------------------------
#define S_QQ 0
#define S_Q  1280
#define S_K  2560
#define S_V  3840
#define S_X1 5120
#define S_H  6400      // 5120 floats
#define SM_TOT 11520

__global__ void __launch_bounds__(256, 4) k_fused(
    const float* __restrict__ temb,
    const float* __restrict__ bo,
    const float* __restrict__ ln1g, const float* __restrict__ ln1b,
    const float* __restrict__ ln2g, const float* __restrict__ ln2b,
    const float* __restrict__ fb1,  const float* __restrict__ fb2,
    const float* __restrict__ lng,  const float* __restrict__ lnb,
    const float* __restrict__ w2c,  const float* __restrict__ b2c,
    const float* __restrict__ w3c,  const float* __restrict__ b3c,
    float* __restrict__ outp)
{
  __shared__ __align__(16) float sm[SM_TOT];

  int tid = threadIdx.x;
  int warp = tid>>5, lane = tid&31;
  long base = (long)blockIdx.x * 768;

  for (int idx=tid; idx<768; idx+=256){
    int e = idx/12, t = idx - e*12;
    sm[S_QQ + e*ST+t] = g_out[base+idx] + __ldg(temb + t*64+e);
  }
  __syncthreads();

  for (int l=0; l<LL; l++){
    const float* wT   = g_wT + l*WTL;
    const float* bo_  = bo  + l*64;
    const float* ln1g_= ln1g+ l*64;  const float* ln1b_= ln1b+ l*64;
    const float* ln2g_= ln2g+ l*64;  const float* ln2b_= ln2b+ l*64;
    const float* fb1_ = fb1 + l*256;
    const float* fb2_ = fb2 + l*64;
    const float* lng_ = lng + l*64;  const float* lnb_ = lnb + l*64;

    // ---- Q,K,V split-k: 192 threads = 3 mats x (32 e2 x 2 kgroups) ----
    if (tid < 192){
      int m  = tid >> 6;
      int kg = (tid >> 5) & 1;
      int e2 = tid & 31;
      const float* WT = wT + m*4096;   // WqT/WkT/WvT, [64][64]
      int bi = m*2 + kg;
      float* pb = (bi < 5) ? (sm + S_H + bi*896) : (sm + S_X1);
      u64t A[6]={0,0,0,0,0,0}, B[6]={0,0,0,0,0,0};
      gemm2T(sm + S_QQ, WT, 64, e2, e2+32, kg*32, 32, A, B);
      store6(pb + e2*PT, A);
      store6(pb + (e2+32)*PT, B);
    }
    __syncthreads();
    // sum partials -> Q,K,V
    for (int idx=tid; idx<2304; idx+=256){
      int m = idx/768, r = idx - m*768;
      int e = r/12, t = r - e*12;
      const float* p0 = (m*2   < 5) ? (sm + S_H + (m*2  )*896) : (sm + S_X1);
      const float* p1 = (m*2+1 < 5) ? (sm + S_H + (m*2+1)*896) : (sm + S_X1);
      float v = p0[e*PT+t] + p1[e*PT+t];
      float* dst = sm + (m==0 ? S_Q : (m==1 ? S_K : S_V));
      dst[e*ST+t] = v;
    }
    __syncthreads();

    // ---- attention scores: 192 threads, 3 scores each; q row in regs ----
    if (tid < 192){
      int h = tid / 48;
      int rem = tid - h*48;
      int t2 = rem >> 2;
      int sq = (rem & 3) * 3;
      const float* qp = sm + S_Q + (h*16)*ST + t2;
      float q[16];
      #pragma unroll
      for (int d=0; d<16; d++) q[d] = qp[d*ST];
      #pragma unroll
      for (int j=0;j<3;j++){
        int s = sq + j;
        const float* kp = sm + S_K + (h*16)*ST + s;
        float sum=0.f;
        #pragma unroll
        for (int d=0;d<16;d++) sum += q[d]*kp[d*ST];
        sm[S_H + (h*12+t2)*12 + s] = sum*0.25f;
      }
    }
    __syncthreads();
    if (tid < 48){
      float* row = sm + S_H + tid*12;
      float mxv = row[0];
      #pragma unroll
      for (int s=1;s<12;s++) mxv = fmaxf(mxv,row[s]);
      float evv[12]; float sum=0.f;
      #pragma unroll
      for (int s=0;s<12;s++){ evv[s]=__expf(row[s]-mxv); sum+=evv[s]; }
      float inv = 1.f/sum;
      #pragma unroll
      for (int s=0;s<12;s++) row[s]=evv[s]*inv;
    }
    __syncthreads();

    // ---- ctx = att @ V (float4 loads; into S_Q) ----
    for (int idx=tid; idx<768; idx+=256){
      int e = idx/12, t2 = idx - e*12, h = e>>4;
      const float4* a4 = (const float4*)(sm + S_H + (h*12+t2)*12);
      const float4* v4 = (const float4*)(sm + S_V + e*ST);
      float4 a0=a4[0], a1=a4[1], a2=a4[2];
      float4 v0=v4[0], v1=v4[1], v2=v4[2];
      float sum = a0.x*v0.x + a0.y*v0.y + a0.z*v0.z + a0.w*v0.w
                + a1.x*v1.x + a1.y*v1.y + a1.z*v1.z + a1.w*v1.w
                + a2.x*v2.x + a2.y*v2.y + a2.z*v2.z + a2.w*v2.w;
      sm[S_Q + e*ST+t2] = sum;
    }
    __syncthreads();

    // ---- attn_out = ctx @ Wo : 128 threads, 4 kgroups; partials -> S_H ----
    if (tid < 128){
      int kg = tid>>5, e2 = tid&31;
      u64t A[6]={0,0,0,0,0,0}, B[6]={0,0,0,0,0,0};
      gemm2T(sm + S_Q, wT + 12288, 64, e2, e2+32, kg*16, 16, A, B);
      float* pb = sm + S_H + kg*896;
      store6(pb + e2*PT, A);
      store6(pb + (e2+32)*PT, B);
    }
    __syncthreads();

    // ---- LN1 merged with Wo-sum + bias + residual; -> S_X1 ----
    for (int t = warp; t < 12; t += 8){
      int e0 = lane, e1 = lane+32;
      float v0 = sm[S_H+e0*PT+t]+sm[S_H+896+e0*PT+t]+sm[S_H+1792+e0*PT+t]+sm[S_H+2688+e0*PT+t]
               + bo_[e0] + sm[S_QQ+e0*ST+t];
      float v1 = sm[S_H+e1*PT+t]+sm[S_H+896+e1*PT+t]+sm[S_H+1792+e1*PT+t]+sm[S_H+2688+e1*PT+t]
               + bo_[e1] + sm[S_QQ+e1*ST+t];
      float s  = warp_sum(v0+v1);
      float s2 = warp_sum(v0*v0+v1*v1);
      float mean = s*(1.f/64.f);
      float var  = s2*(1.f/64.f) - mean*mean;
      float r = rsqrtf(var + 1e-5f);
      sm[S_X1+e0*ST+t] = (v0-mean)*r*ln1g_[e0] + ln1b_[e0];
      sm[S_X1+e1*ST+t] = (v1-mean)*r*ln1g_[e1] + ln1b_[e1];
    }
    __syncthreads();

    // ---- FF1: 128 threads, cols (f, f+128), k=64; relu -> S_H ----
    if (tid < 128){
      int f = tid;
      u64t A[6]={0,0,0,0,0,0}, B[6]={0,0,0,0,0,0};
      gemm2T(sm + S_X1, wT + 16384, 64, f, f+128, 0, 64, A, B);
      float ba = fb1_[f], bb2 = fb1_[f+128];
      float* dA = sm + S_H + f*ST;
      float* dB = sm + S_H + (f+128)*ST;
      #pragma unroll
      for (int p=0;p<6;p++){
        float2 va = *(const float2*)&A[p];
        float2 vb = *(const float2*)&B[p];
        va.x = fmaxf(va.x+ba,0.f);  va.y = fmaxf(va.y+ba,0.f);
        vb.x = fmaxf(vb.x+bb2,0.f); vb.y = fmaxf(vb.y+bb2,0.f);
        ((float2*)dA)[p] = va;
        ((float2*)dB)[p] = vb;
      }
    }
    __syncthreads();

    // ---- FF2: 128 threads, 4 kgroups of 64; partials -> S_Q region ----
    if (tid < 128){
      int kg = tid>>5, e2 = tid&31;
      u64t A[6]={0,0,0,0,0,0}, B[6]={0,0,0,0,0,0};
      gemm2T(sm + S_H, wT + 32768, 256, e2, e2+32, kg*64, 64, A, B);
      float* pb = sm + S_Q + kg*896;
      store6(pb + e2*PT, A);
      store6(pb + (e2+32)*PT, B);
    }
    __syncthreads();

    // ---- LN2 merged with FF2-sum + bias + residual(X1); -> S_X1 ----
    for (int t = warp; t < 12; t += 8){
      int e0 = lane, e1 = lane+32;
      float v0 = sm[S_Q+e0*PT+t]+sm[S_Q+896+e0*PT+t]+sm[S_Q+1792+e0*PT+t]+sm[S_Q+2688+e0*PT+t]
               + fb2_[e0] + sm[S_X1+e0*ST+t];
      float v1 = sm[S_Q+e1*PT+t]+sm[S_Q+896+e1*PT+t]+sm[S_Q+1792+e1*PT+t]+sm[S_Q+2688+e1*PT+t]
               + fb2_[e1] + sm[S_X1+e1*ST+t];
      float s  = warp_sum(v0+v1);
      float s2 = warp_sum(v0*v0+v1*v1);
      float mean = s*(1.f/64.f);
      float var  = s2*(1.f/64.f) - mean*mean;
      float r = rsqrtf(var + 1e-5f);
      sm[S_X1+e0*ST+t] = (v0-mean)*r*ln2g_[e0] + ln2b_[e0];
      sm[S_X1+e1*ST+t] = (v1-mean)*r*ln2g_[e1] + ln2b_[e1];
    }
    __syncthreads();

    // ---- LN3 merged with residual (QQ - temb) ----
    for (int t = warp; t < 12; t += 8){
      int e0 = lane, e1 = lane+32;
      float te0 = __ldg(temb + t*64+e0), te1 = __ldg(temb + t*64+e1);
      float v0 = sm[S_X1+e0*ST+t] + sm[S_QQ+e0*ST+t] - te0;
      float v1 = sm[S_X1+e1*ST+t] + sm[S_QQ+e1*ST+t] - te1;
      float s  = warp_sum(v0+v1);
      float s2 = warp_sum(v0*v0+v1*v1);
      float mean = s*(1.f/64.f);
      float var  = s2*(1.f/64.f) - mean*mean;
      float r = rsqrtf(var + 1e-5f);
      float o0 = (v0-mean)*r*lng_[e0] + lnb_[e0];
      float o1 = (v1-mean)*r*lng_[e1] + lnb_[e1];
      if (l+1 < LL){
        sm[S_QQ+e0*ST+t] = o0 + te0;
        sm[S_QQ+e1*ST+t] = o1 + te1;
      } else {
        sm[S_K+e0*ST+t] = o0;
        sm[S_K+e1*ST+t] = o1;
      }
    }
    __syncthreads();
  }

  // ---- head: conv2 over t (relu) + conv3 over e. out in S_K ----
  if (tid < 192){
    int o = tid>>4, es = (tid&15)*4;
    float w2row[12];
    #pragma unroll
    for (int t=0;t<12;t++) w2row[t] = __ldg(w2c + o*12 + t);
    float b2v = __ldg(b2c + o);
    float acc = 0.f;
    #pragma unroll
    for (int q=0;q<4;q++){
      int e = es + q;
      const float* rowp = sm + S_K + e*ST;
      float v = b2v;
      #pragma unroll
      for (int t=0;t<12;t++) v += rowp[t]*w2row[t];
      v = fmaxf(v, 0.f);
      acc += v * __ldg(w3c + e);
    }
    #pragma unroll
    for (int off=8; off; off>>=1) acc += __shfl_xor_sync(0xffffffffu, acc, off);
    if ((tid&15)==0) outp[(long)blockIdx.x*12 + o] = acc + __ldg(b3c);
  }
}

// ---------------------------------------------------------------------------
extern "C" void kernel_launch(void* const* d_in, const int* in_sizes, int n_in,
                              void* d_out, int out_size) {
  const float* x       = (const float*)d_in[0];
  const int*   adj     = (const int*)  d_in[1];
  const float* gat_W2  = (const float*)d_in[2];
  const float* gat_a   = (const float*)d_in[3];
  const float* gat_b   = (const float*)d_in[4];
  const float* conv1_w = (const float*)d_in[5];
  const float* conv1_b = (const float*)d_in[6];
  const float* temb    = (const float*)d_in[7];
  const float* Wq      = (const float*)d_in[8];
  const float* Wk      = (const float*)d_in[9];
  const float* Wv      = (const float*)d_in[10];
  const float* Wo      = (const float*)d_in[11];
  const float* bo      = (const float*)d_in[12];
  const float* ln1_g   = (const float*)d_in[13];
  const float* ln1_b   = (const float*)d_in[14];
  const float* ln2_g   = (const float*)d_in[15];
  const float* ln2_b   = (const float*)d_in[16];
  const float* ff_w1   = (const float*)d_in[17];
  const float* ff_b1   = (const float*)d_in[18];
  const float* ff_w2   = (const float*)d_in[19];
  const float* ff_b2   = (const float*)d_in[20];
  const float* lng     = (const float*)d_in[21];
  const float* lnb     = (const float*)d_in[22];
  const float* conv2_w = (const float*)d_in[23];
  const float* conv2_b = (const float*)d_in[24];
  const float* conv3_w = (const float*)d_in[25];
  const float* conv3_b = (const float*)d_in[26];
  float* outp = (float*)d_out;

  k_tw<<<(2*WTL + 255)/256, 256>>>(Wq, Wk, Wv, Wo, ff_w1, ff_w2);

  dim3 g1(BB, (NV + 1) / 2);
  k_gat<<<g1, 128>>>(x, adj, gat_W2, gat_a, gat_b, conv1_w, conv1_b);

  k_fused<<<BB*NV, 256>>>(temb, bo,
                          ln1_g, ln1_b, ln2_g, ln2_b,
                          ff_b1, ff_b2,
                          lng, lnb,
                          conv2_w, conv2_b, conv3_w, conv3_b, outp);
}

// round 10
// speedup vs baseline: 1.3691x; 1.3691x over previous
#include <cuda_runtime.h>

#define BB 8
#define NV 207
#define TT 12
#define LL 2
#define NGH 8
#define ALPHA 0.2f
#define NN (NV*NV)
#define ST 20   // k-major stride for activation buffers (floats)
#define PT 14   // stride for partial-sum buffers
#define XR 418  // GAT slab row stride (per t)

typedef unsigned long long u64t;

__device__ __forceinline__ float warp_sum(float v){
  #pragma unroll
  for (int o=16;o;o>>=1) v += __shfl_xor_sync(0xffffffffu, v, o);
  return v;
}
__device__ __forceinline__ u64t pack2(float v){
  u64t r; asm("mov.b64 %0, {%1, %1};" : "=l"(r) : "f"(v)); return r;
}
__device__ __forceinline__ void fma2(u64t &acc, u64t a, u64t b){
  asm("fma.rn.f32x2 %0, %1, %2, %0;" : "+l"(acc) : "l"(a), "l"(b));
}

// 2-column GEMM (R8 version: per-lane coalesced weight LDG).
__device__ __forceinline__ void gemm2(const float* __restrict__ sIn,
                                      const float* __restrict__ W, int ldw,
                                      int c0, int c1, int k0, int nk,
                                      u64t A[6], u64t Bc[6]){
  #pragma unroll 4
  for (int k=k0; k<k0+nk; k++){
    const float* wr = W + (long)k*ldw;
    u64t wa = pack2(__ldg(wr+c0));
    u64t wb = pack2(__ldg(wr+c1));
    const ulonglong2* a = (const ulonglong2*)(sIn + k*ST);
    ulonglong2 v0 = a[0], v1 = a[1], v2 = a[2];
    fma2(A[0], v0.x, wa); fma2(Bc[0], v0.x, wb);
    fma2(A[1], v0.y, wa); fma2(Bc[1], v0.y, wb);
    fma2(A[2], v1.x, wa); fma2(Bc[2], v1.x, wb);
    fma2(A[3], v1.y, wa); fma2(Bc[3], v1.y, wb);
    fma2(A[4], v2.x, wa); fma2(Bc[4], v2.x, wb);
    fma2(A[5], v2.y, wa); fma2(Bc[5], v2.y, wb);
  }
}

__device__ __forceinline__ void store6(float* dst, const u64t A[6]){
  #pragma unroll
  for (int p=0;p<6;p++) ((float2*)dst)[p] = *(const float2*)&A[p];
}

// ---------------------------------------------------------------------------
// Single kernel: GAT row + conv1 + 2 transformer layers + conv2/conv3 head.
// grid 1656 (=B*N), block 256. smem arena 46KB.
// GAT slab lives in S_H (dead until QKV); adj row in S_X1.
// ---------------------------------------------------------------------------
#define S_QQ 0
#define S_Q  1280
#define S_K  2560
#define S_V  3840
#define S_X1 5120
#define S_H  6400      // 5120 floats
#define SM_TOT 11520

__global__ void __launch_bounds__(256, 4) k_fused(
    const float* __restrict__ x,
    const int*   __restrict__ adj,
    const float* __restrict__ W2,  const float* __restrict__ ga,
    const float* __restrict__ gb,
    const float* __restrict__ w1c, const float* __restrict__ b1c,
    const float* __restrict__ temb,
    const float* __restrict__ Wq, const float* __restrict__ Wk,
    const float* __restrict__ Wv, const float* __restrict__ Wo,
    const float* __restrict__ bo,
    const float* __restrict__ ln1g, const float* __restrict__ ln1b,
    const float* __restrict__ ln2g, const float* __restrict__ ln2b,
    const float* __restrict__ fw1, const float* __restrict__ fb1,
    const float* __restrict__ fw2, const float* __restrict__ fb2,
    const float* __restrict__ lng, const float* __restrict__ lnb,
    const float* __restrict__ w2c, const float* __restrict__ b2c,
    const float* __restrict__ w3c, const float* __restrict__ b3c,
    float* __restrict__ outp)
{
  __shared__ __align__(16) float sm[SM_TOT];

  int tid = threadIdx.x;
  int warp = tid>>5, lane = tid&31;
  int bid = blockIdx.x;
  int b = bid / NV, i = bid - b*NV;

  // ===== GAT phase: slab into S_H (transposed [t][2n+c]), adj into S_X1 =====
  const float* xb = x + (long)b*2*NV*TT;
  for (int idx=tid; idx<2*NV*TT; idx+=256){
    int c = idx/(NV*TT); int r = idx - c*NV*TT;
    int n = r/TT, t = r - n*TT;
    sm[S_H + t*XR + 2*n + c] = xb[idx];
  }
  int* adjs = (int*)(sm + S_X1);
  for (int idx=tid; idx<NV; idx+=256)
    adjs[idx] = adj[((long)(b*NV)+i)*NV + idx];
  __syncthreads();

  for (int t = warp; t < 12; t += 8){
    const float* xrow = sm + S_H + t*XR;

    float acc0=0.f, acc1=0.f;
    #pragma unroll
    for (int hg=0; hg<2; hg++){
      float w2r[4][4][2], ar[4][2];
      #pragma unroll
      for (int hh=0;hh<4;hh++){
        int h = hg*4+hh;
        #pragma unroll
        for (int k=0;k<4;k++){
          w2r[hh][k][0]=__ldg(W2+(h*4+k)*2+0);
          w2r[hh][k][1]=__ldg(W2+(h*4+k)*2+1);
        }
        ar[hh][0]=__ldg(ga+h*2); ar[hh][1]=__ldg(ga+h*2+1);
      }
      float d[4]={0,0,0,0}, n0[4]={0,0,0,0}, n1[4]={0,0,0,0};
      #pragma unroll
      for (int jj=0; jj<7; jj++){
        int j = jj*32 + lane;
        bool valid = j < NV;
        int jc = valid ? j : 0;
        bool ok = valid && (adjs[jc] > 0);
        int r0 = 2*(i*NV + jc);
        int r1 = r0 + 1;
        int a0 = (r0 < NN) ? (r0 / NV) : ((r0 - NN) % NV);
        int a1 = (r1 < NN) ? (r1 / NV) : ((r1 - NN) % NV);
        float2 ca = *(const float2*)(xrow + 2*a0);
        float2 cb = *(const float2*)(xrow + 2*a1);
        float2 xj = *(const float2*)(xrow + 2*jc);
        #pragma unroll
        for (int hh=0;hh<4;hh++){
          float we0 = ca.x*w2r[hh][0][0] + ca.y*w2r[hh][1][0] + cb.x*w2r[hh][2][0] + cb.y*w2r[hh][3][0];
          float we1 = ca.x*w2r[hh][0][1] + ca.y*w2r[hh][1][1] + cb.x*w2r[hh][2][1] + cb.y*w2r[hh][3][1];
          we0 = (we0 > 0.f) ? we0 : ALPHA*we0;
          we1 = (we1 > 0.f) ? we1 : ALPHA*we1;
          float e = we0*ar[hh][0] + we1*ar[hh][1];
          float w = ok ? __expf(e) : 0.f;
          d[hh]  += w;
          n0[hh] += w*xj.x;
          n1[hh] += w*xj.y;
        }
      }
      #pragma unroll
      for (int off=16; off; off>>=1){
        #pragma unroll
        for (int hh=0;hh<4;hh++){
          d[hh]  += __shfl_xor_sync(0xffffffffu, d[hh],  off);
          n0[hh] += __shfl_xor_sync(0xffffffffu, n0[hh], off);
          n1[hh] += __shfl_xor_sync(0xffffffffu, n1[hh], off);
        }
      }
      #pragma unroll
      for (int hh=0;hh<4;hh++){
        int h = hg*4+hh;
        float inv = 1.0f/d[hh];
        float z0 = n0[hh]*inv + __ldg(gb+h*2+0);
        float z1 = n1[hh]*inv + __ldg(gb+h*2+1);
        acc0 += 1.f - __fdividef(2.f, __expf(2.f*z0)+1.f);
        acc1 += 1.f - __fdividef(2.f, __expf(2.f*z1)+1.f);
      }
    }
    acc0 *= 0.125f; acc1 *= 0.125f;

    float xi0 = xrow[2*i], xi1 = xrow[2*i+1];
    #pragma unroll
    for (int r=0;r<2;r++){
      int e = lane + r*32;
      float v = xi0*__ldg(w1c+e) + xi1*__ldg(w1c+64+e)
              + acc0*__ldg(w1c+128+e) + acc1*__ldg(w1c+192+e) + __ldg(b1c+e);
      sm[S_QQ + e*ST + t] = v + __ldg(temb + t*64+e);
    }
  }
  __syncthreads();

  // ===== Transformer layers =====
  for (int l=0; l<LL; l++){
    const float* Wq_  = Wq  + l*4096;
    const float* Wk_  = Wk  + l*4096;
    const float* Wv_  = Wv  + l*4096;
    const float* Wo_  = Wo  + l*4096;
    const float* bo_  = bo  + l*64;
    const float* ln1g_= ln1g+ l*64;  const float* ln1b_= ln1b+ l*64;
    const float* ln2g_= ln2g+ l*64;  const float* ln2b_= ln2b+ l*64;
    const float* fw1_ = fw1 + l*16384; const float* fb1_ = fb1 + l*256;
    const float* fw2_ = fw2 + l*16384; const float* fb2_ = fb2 + l*64;
    const float* lng_ = lng + l*64;  const float* lnb_ = lnb + l*64;

    // ---- Q,K,V split-k: 192 threads = 3 mats x (32 e2 x 2 kgroups) ----
    if (tid < 192){
      int m  = tid >> 6;
      int kg = (tid >> 5) & 1;
      int e2 = tid & 31;
      const float* W = (m==0 ? Wq_ : (m==1 ? Wk_ : Wv_));
      int bi = m*2 + kg;
      float* pb = (bi < 5) ? (sm + S_H + bi*896) : (sm + S_X1);
      u64t A[6]={0,0,0,0,0,0}, B[6]={0,0,0,0,0,0};
      gemm2(sm + S_QQ, W, 64, e2, e2+32, kg*32, 32, A, B);
      store6(pb + e2*PT, A);
      store6(pb + (e2+32)*PT, B);
    }
    __syncthreads();
    // sum partials -> Q,K,V
    for (int idx=tid; idx<2304; idx+=256){
      int m = idx/768, r = idx - m*768;
      int e = r/12, t = r - e*12;
      const float* p0 = (m*2   < 5) ? (sm + S_H + (m*2  )*896) : (sm + S_X1);
      const float* p1 = (m*2+1 < 5) ? (sm + S_H + (m*2+1)*896) : (sm + S_X1);
      float v = p0[e*PT+t] + p1[e*PT+t];
      float* dst = sm + (m==0 ? S_Q : (m==1 ? S_K : S_V));
      dst[e*ST+t] = v;
    }
    __syncthreads();

    // ---- attention scores: 192 threads, 3 scores each ----
    if (tid < 192){
      int h = tid / 48;
      int rem = tid - h*48;
      int t2 = rem >> 2;
      int sq = (rem & 3) * 3;
      const float* qp = sm + S_Q + (h*16)*ST + t2;
      float q[16];
      #pragma unroll
      for (int d=0; d<16; d++) q[d] = qp[d*ST];
      #pragma unroll
      for (int j=0;j<3;j++){
        int s = sq + j;
        const float* kp = sm + S_K + (h*16)*ST + s;
        float sum=0.f;
        #pragma unroll
        for (int d=0;d<16;d++) sum += q[d]*kp[d*ST];
        sm[S_H + (h*12+t2)*12 + s] = sum*0.25f;
      }
    }
    __syncthreads();
    if (tid < 48){
      float* row = sm + S_H + tid*12;
      float mxv = row[0];
      #pragma unroll
      for (int s=1;s<12;s++) mxv = fmaxf(mxv,row[s]);
      float evv[12]; float sum=0.f;
      #pragma unroll
      for (int s=0;s<12;s++){ evv[s]=__expf(row[s]-mxv); sum+=evv[s]; }
      float inv = 1.f/sum;
      #pragma unroll
      for (int s=0;s<12;s++) row[s]=evv[s]*inv;
    }
    __syncthreads();

    // ---- ctx = att @ V (float4 loads; into S_Q) ----
    for (int idx=tid; idx<768; idx+=256){
      int e = idx/12, t2 = idx - e*12, h = e>>4;
      const float4* a4 = (const float4*)(sm + S_H + (h*12+t2)*12);
      const float4* v4 = (const float4*)(sm + S_V + e*ST);
      float4 a0=a4[0], a1=a4[1], a2=a4[2];
      float4 v0=v4[0], v1=v4[1], v2=v4[2];
      float sum = a0.x*v0.x + a0.y*v0.y + a0.z*v0.z + a0.w*v0.w
                + a1.x*v1.x + a1.y*v1.y + a1.z*v1.z + a1.w*v1.w
                + a2.x*v2.x + a2.y*v2.y + a2.z*v2.z + a2.w*v2.w;
      sm[S_Q + e*ST+t2] = sum;
    }
    __syncthreads();

    // ---- attn_out = ctx @ Wo : 128 threads, 4 kgroups; partials -> S_H ----
    if (tid < 128){
      int kg = tid>>5, e2 = tid&31;
      u64t A[6]={0,0,0,0,0,0}, B[6]={0,0,0,0,0,0};
      gemm2(sm + S_Q, Wo_, 64, e2, e2+32, kg*16, 16, A, B);
      float* pb = sm + S_H + kg*896;
      store6(pb + e2*PT, A);
      store6(pb + (e2+32)*PT, B);
    }
    __syncthreads();

    // ---- LN1 merged with Wo-sum + bias + residual; -> S_X1 ----
    for (int t = warp; t < 12; t += 8){
      int e0 = lane, e1 = lane+32;
      float v0 = sm[S_H+e0*PT+t]+sm[S_H+896+e0*PT+t]+sm[S_H+1792+e0*PT+t]+sm[S_H+2688+e0*PT+t]
               + bo_[e0] + sm[S_QQ+e0*ST+t];
      float v1 = sm[S_H+e1*PT+t]+sm[S_H+896+e1*PT+t]+sm[S_H+1792+e1*PT+t]+sm[S_H+2688+e1*PT+t]
               + bo_[e1] + sm[S_QQ+e1*ST+t];
      float s  = warp_sum(v0+v1);
      float s2 = warp_sum(v0*v0+v1*v1);
      float mean = s*(1.f/64.f);
      float var  = s2*(1.f/64.f) - mean*mean;
      float r = rsqrtf(var + 1e-5f);
      sm[S_X1+e0*ST+t] = (v0-mean)*r*ln1g_[e0] + ln1b_[e0];
      sm[S_X1+e1*ST+t] = (v1-mean)*r*ln1g_[e1] + ln1b_[e1];
    }
    __syncthreads();

    // ---- FF1: 128 threads, cols (f, f+128), k=64; relu -> S_H ----
    if (tid < 128){
      int f = tid;
      u64t A[6]={0,0,0,0,0,0}, B[6]={0,0,0,0,0,0};
      gemm2(sm + S_X1, fw1_, 256, f, f+128, 0, 64, A, B);
      float ba = fb1_[f], bb2 = fb1_[f+128];
      float* dA = sm + S_H + f*ST;
      float* dB = sm + S_H + (f+128)*ST;
      #pragma unroll
      for (int p=0;p<6;p++){
        float2 va = *(const float2*)&A[p];
        float2 vb = *(const float2*)&B[p];
        va.x = fmaxf(va.x+ba,0.f);  va.y = fmaxf(va.y+ba,0.f);
        vb.x = fmaxf(vb.x+bb2,0.f); vb.y = fmaxf(vb.y+bb2,0.f);
        ((float2*)dA)[p] = va;
        ((float2*)dB)[p] = vb;
      }
    }
    __syncthreads();

    // ---- FF2: 128 threads, 4 kgroups of 64; partials -> S_Q region ----
    if (tid < 128){
      int kg = tid>>5, e2 = tid&31;
      u64t A[6]={0,0,0,0,0,0}, B[6]={0,0,0,0,0,0};
      gemm2(sm + S_H, fw2_, 64, e2, e2+32, kg*64, 64, A, B);
      float* pb = sm + S_Q + kg*896;
      store6(pb + e2*PT, A);
      store6(pb + (e2+32)*PT, B);
    }
    __syncthreads();

    // ---- LN2 merged with FF2-sum + bias + residual(X1); -> S_X1 ----
    for (int t = warp; t < 12; t += 8){
      int e0 = lane, e1 = lane+32;
      float v0 = sm[S_Q+e0*PT+t]+sm[S_Q+896+e0*PT+t]+sm[S_Q+1792+e0*PT+t]+sm[S_Q+2688+e0*PT+t]
               + fb2_[e0] + sm[S_X1+e0*ST+t];
      float v1 = sm[S_Q+e1*PT+t]+sm[S_Q+896+e1*PT+t]+sm[S_Q+1792+e1*PT+t]+sm[S_Q+2688+e1*PT+t]
               + fb2_[e1] + sm[S_X1+e1*ST+t];
      float s  = warp_sum(v0+v1);
      float s2 = warp_sum(v0*v0+v1*v1);
      float mean = s*(1.f/64.f);
      float var  = s2*(1.f/64.f) - mean*mean;
      float r = rsqrtf(var + 1e-5f);
      sm[S_X1+e0*ST+t] = (v0-mean)*r*ln2g_[e0] + ln2b_[e0];
      sm[S_X1+e1*ST+t] = (v1-mean)*r*ln2g_[e1] + ln2b_[e1];
    }
    __syncthreads();

    // ---- LN3 merged with residual (QQ - temb) ----
    for (int t = warp; t < 12; t += 8){
      int e0 = lane, e1 = lane+32;
      float te0 = __ldg(temb + t*64+e0), te1 = __ldg(temb + t*64+e1);
      float v0 = sm[S_X1+e0*ST+t] + sm[S_QQ+e0*ST+t] - te0;
      float v1 = sm[S_X1+e1*ST+t] + sm[S_QQ+e1*ST+t] - te1;
      float s  = warp_sum(v0+v1);
      float s2 = warp_sum(v0*v0+v1*v1);
      float mean = s*(1.f/64.f);
      float var  = s2*(1.f/64.f) - mean*mean;
      float r = rsqrtf(var + 1e-5f);
      float o0 = (v0-mean)*r*lng_[e0] + lnb_[e0];
      float o1 = (v1-mean)*r*lng_[e1] + lnb_[e1];
      if (l+1 < LL){
        sm[S_QQ+e0*ST+t] = o0 + te0;
        sm[S_QQ+e1*ST+t] = o1 + te1;
      } else {
        sm[S_K+e0*ST+t] = o0;
        sm[S_K+e1*ST+t] = o1;
      }
    }
    __syncthreads();
  }

  // ===== head: conv2 over t (relu) + conv3 over e. out in S_K =====
  if (tid < 192){
    int o = tid>>4, es = (tid&15)*4;
    float w2row[12];
    #pragma unroll
    for (int t=0;t<12;t++) w2row[t] = __ldg(w2c + o*12 + t);
    float b2v = __ldg(b2c + o);
    float acc = 0.f;
    #pragma unroll
    for (int q=0;q<4;q++){
      int e = es + q;
      const float* rowp = sm + S_K + e*ST;
      float v = b2v;
      #pragma unroll
      for (int t=0;t<12;t++) v += rowp[t]*w2row[t];
      v = fmaxf(v, 0.f);
      acc += v * __ldg(w3c + e);
    }
    #pragma unroll
    for (int off=8; off; off>>=1) acc += __shfl_xor_sync(0xffffffffu, acc, off);
    if ((tid&15)==0) outp[(long)bid*12 + o] = acc + __ldg(b3c);
  }
}

// ---------------------------------------------------------------------------
extern "C" void kernel_launch(void* const* d_in, const int* in_sizes, int n_in,
                              void* d_out, int out_size) {
  const float* x       = (const float*)d_in[0];
  const int*   adj     = (const int*)  d_in[1];
  const float* gat_W2  = (const float*)d_in[2];
  const float* gat_a   = (const float*)d_in[3];
  const float* gat_b   = (const float*)d_in[4];
  const float* conv1_w = (const float*)d_in[5];
  const float* conv1_b = (const float*)d_in[6];
  const float* temb    = (const float*)d_in[7];
  const float* Wq      = (const float*)d_in[8];
  const float* Wk      = (const float*)d_in[9];
  const float* Wv      = (const float*)d_in[10];
  const float* Wo      = (const float*)d_in[11];
  const float* bo      = (const float*)d_in[12];
  const float* ln1_g   = (const float*)d_in[13];
  const float* ln1_b   = (const float*)d_in[14];
  const float* ln2_g   = (const float*)d_in[15];
  const float* ln2_b   = (const float*)d_in[16];
  const float* ff_w1   = (const float*)d_in[17];
  const float* ff_b1   = (const float*)d_in[18];
  const float* ff_w2   = (const float*)d_in[19];
  const float* ff_b2   = (const float*)d_in[20];
  const float* lng     = (const float*)d_in[21];
  const float* lnb     = (const float*)d_in[22];
  const float* conv2_w = (const float*)d_in[23];
  const float* conv2_b = (const float*)d_in[24];
  const float* conv3_w = (const float*)d_in[25];
  const float* conv3_b = (const float*)d_in[26];
  float* outp = (float*)d_out;

  k_fused<<<BB*NV, 256>>>(x, adj, gat_W2, gat_a, gat_b, conv1_w, conv1_b,
                          temb, Wq, Wk, Wv, Wo, bo,
                          ln1_g, ln1_b, ln2_g, ln2_b,
                          ff_w1, ff_b1, ff_w2, ff_b2,
                          lng, lnb,
                          conv2_w, conv2_b, conv3_w, conv3_b, outp);
}

// round 11
// speedup vs baseline: 1.4913x; 1.0892x over previous
#include <cuda_runtime.h>

#define BB 8
#define NV 207
#define TT 12
#define LL 2
#define NGH 8
#define ALPHA 0.2f
#define NN (NV*NV)
#define ST 20   // k-major stride for activation buffers (floats)
#define PT 14   // stride for partial-sum buffers
#define XR 418  // GAT slab row stride (per t)

typedef unsigned long long u64t;

// scratch: gat output (B*N groups, layout per group: e*12+t)
__device__ float g_out[BB*NV*TT*64];

__device__ __forceinline__ float warp_sum(float v){
  #pragma unroll
  for (int o=16;o;o>>=1) v += __shfl_xor_sync(0xffffffffu, v, o);
  return v;
}
__device__ __forceinline__ u64t pack2(float v){
  u64t r; asm("mov.b64 %0, {%1, %1};" : "=l"(r) : "f"(v)); return r;
}
__device__ __forceinline__ void fma2(u64t &acc, u64t a, u64t b){
  asm("fma.rn.f32x2 %0, %1, %2, %0;" : "+l"(acc) : "l"(a), "l"(b));
}

// ---------------------------------------------------------------------------
// K1: GAT + conv1. Block = (b, 4-row chunk), 256 threads.
// x[b] staged TRANSPOSED [t][2n+c]; GAT weights staged in smem.
// ---------------------------------------------------------------------------
__global__ void __launch_bounds__(256) k_gat(
    const float* __restrict__ x,      // (B,C,N,T)
    const int*   __restrict__ adj,    // (B,N,N)
    const float* __restrict__ W2,     // (8,4,2)
    const float* __restrict__ ga,     // (8,2)
    const float* __restrict__ gb,     // (8,2)
    const float* __restrict__ w1,     // (4,64)
    const float* __restrict__ b1)     // (64)
{
  __shared__ float xsa[TT*XR];     // [t][2n+c]
  __shared__ int   adjs[4*NV];
  __shared__ float w1s[256];
  __shared__ float b1s[64];
  __shared__ float sW2[64];
  __shared__ float sga[16];
  __shared__ float sgb[16];

  int b  = blockIdx.x;
  int i0 = blockIdx.y * 4;
  int tid = threadIdx.x;

  const float* xb = x + (long)b*2*NV*TT;
  for (int idx=tid; idx<2*NV*TT; idx+=256){
    int c = idx/(NV*TT); int r = idx - c*NV*TT;
    int n = r/TT, t = r - n*TT;
    xsa[t*XR + 2*n + c] = xb[idx];
  }
  int nrows = (NV - i0) < 4 ? (NV - i0) : 4;
  for (int idx=tid; idx<nrows*NV; idx+=256){
    int ii = idx / NV, j = idx - ii*NV;
    adjs[ii*NV+j] = adj[((long)b*NV + i0+ii)*NV + j];
  }
  if (tid<256) w1s[tid]=w1[tid];
  if (tid<64) b1s[tid]=b1[tid];
  if (tid>=64 && tid<128) sW2[tid-64]=W2[tid-64];
  if (tid>=128 && tid<144) sga[tid-128]=ga[tid-128];
  if (tid>=144 && tid<160) sgb[tid-144]=gb[tid-144];
  __syncthreads();

  int warp = tid>>5, lane = tid&31;

  for (int task = warp; task < 48; task += 8){
    int t  = task % 12;
    int ii = task / 12;
    int i  = i0 + ii;
    if (i >= NV) continue;
    const int* arow = adjs + ii*NV;
    const float* xrow = xsa + t*XR;

    float acc0=0.f, acc1=0.f;
    #pragma unroll
    for (int hg=0; hg<2; hg++){
      float w2r[4][4][2], ar[4][2];
      #pragma unroll
      for (int hh=0;hh<4;hh++){
        int h = hg*4+hh;
        #pragma unroll
        for (int k=0;k<4;k++){
          w2r[hh][k][0]=sW2[(h*4+k)*2+0];
          w2r[hh][k][1]=sW2[(h*4+k)*2+1];
        }
        ar[hh][0]=sga[h*2]; ar[hh][1]=sga[h*2+1];
      }
      float d[4]={0,0,0,0}, n0[4]={0,0,0,0}, n1[4]={0,0,0,0};
      #pragma unroll
      for (int jj=0; jj<7; jj++){
        int j = jj*32 + lane;
        bool valid = j < NV;
        int jc = valid ? j : 0;
        bool ok = valid && (arow[jc] > 0);
        int r0 = 2*(i*NV + jc);
        int r1 = r0 + 1;
        int a0 = (r0 < NN) ? (r0 / NV) : ((r0 - NN) % NV);
        int a1 = (r1 < NN) ? (r1 / NV) : ((r1 - NN) % NV);
        float2 ca = *(const float2*)(xrow + 2*a0);
        float2 cb = *(const float2*)(xrow + 2*a1);
        float2 xj = *(const float2*)(xrow + 2*jc);
        #pragma unroll
        for (int hh=0;hh<4;hh++){
          float we0 = ca.x*w2r[hh][0][0] + ca.y*w2r[hh][1][0] + cb.x*w2r[hh][2][0] + cb.y*w2r[hh][3][0];
          float we1 = ca.x*w2r[hh][0][1] + ca.y*w2r[hh][1][1] + cb.x*w2r[hh][2][1] + cb.y*w2r[hh][3][1];
          we0 = (we0 > 0.f) ? we0 : ALPHA*we0;
          we1 = (we1 > 0.f) ? we1 : ALPHA*we1;
          float e = we0*ar[hh][0] + we1*ar[hh][1];
          float w = ok ? __expf(e) : 0.f;
          d[hh]  += w;
          n0[hh] += w*xj.x;
          n1[hh] += w*xj.y;
        }
      }
      #pragma unroll
      for (int off=16; off; off>>=1){
        #pragma unroll
        for (int hh=0;hh<4;hh++){
          d[hh]  += __shfl_xor_sync(0xffffffffu, d[hh],  off);
          n0[hh] += __shfl_xor_sync(0xffffffffu, n0[hh], off);
          n1[hh] += __shfl_xor_sync(0xffffffffu, n1[hh], off);
        }
      }
      #pragma unroll
      for (int hh=0;hh<4;hh++){
        int h = hg*4+hh;
        float inv = 1.0f/d[hh];
        float z0 = n0[hh]*inv + sgb[h*2+0];
        float z1 = n1[hh]*inv + sgb[h*2+1];
        acc0 += 1.f - __fdividef(2.f, __expf(2.f*z0)+1.f);
        acc1 += 1.f - __fdividef(2.f, __expf(2.f*z1)+1.f);
      }
    }
    acc0 *= 0.125f; acc1 *= 0.125f;

    float xi0 = xrow[2*i], xi1 = xrow[2*i+1];
    long obase = (long)(b*NV + i)*768;
    #pragma unroll
    for (int r=0;r<2;r++){
      int e = lane + r*32;
      g_out[obase + e*12 + t] = xi0*w1s[e] + xi1*w1s[64+e]
                              + acc0*w1s[128+e] + acc1*w1s[192+e] + b1s[e];
    }
  }
}

// ---------------------------------------------------------------------------
// 2-column GEMM (R8 version: per-lane coalesced weight LDG).
// ---------------------------------------------------------------------------
__device__ __forceinline__ void gemm2(const float* __restrict__ sIn,
                                      const float* __restrict__ W, int ldw,
                                      int c0, int c1, int k0, int nk,
                                      u64t A[6], u64t Bc[6]){
  #pragma unroll 4
  for (int k=k0; k<k0+nk; k++){
    const float* wr = W + (long)k*ldw;
    u64t wa = pack2(__ldg(wr+c0));
    u64t wb = pack2(__ldg(wr+c1));
    const ulonglong2* a = (const ulonglong2*)(sIn + k*ST);
    ulonglong2 v0 = a[0], v1 = a[1], v2 = a[2];
    fma2(A[0], v0.x, wa); fma2(Bc[0], v0.x, wb);
    fma2(A[1], v0.y, wa); fma2(Bc[1], v0.y, wb);
    fma2(A[2], v1.x, wa); fma2(Bc[2], v1.x, wb);
    fma2(A[3], v1.y, wa); fma2(Bc[3], v1.y, wb);
    fma2(A[4], v2.x, wa); fma2(Bc[4], v2.x, wb);
    fma2(A[5], v2.y, wa); fma2(Bc[5], v2.y, wb);
  }
}

__device__ __forceinline__ void store6(float* dst, const u64t A[6]){
  #pragma unroll
  for (int p=0;p<6;p++) ((float2*)dst)[p] = *(const float2*)&A[p];
}

// ---------------------------------------------------------------------------
// K2: BOTH transformer layers + conv2/conv3 head fused (exact R8 body).
// grid 1656 (=B*N), block 256. smem arena 46KB.
// ---------------------------------------------------------------------------
#define S_QQ 0
#define S_Q  1280
#define S_K  2560
#define S_V  3840
#define S_X1 5120
#define S_H  6400      // 5120 floats
#define SM_TOT 11520

__global__ void __launch_bounds__(256, 4) k_fused(
    const float* __restrict__ temb,
    const float* __restrict__ Wq, const float* __restrict__ Wk,
    const float* __restrict__ Wv, const float* __restrict__ Wo,
    const float* __restrict__ bo,
    const float* __restrict__ ln1g, const float* __restrict__ ln1b,
    const float* __restrict__ ln2g, const float* __restrict__ ln2b,
    const float* __restrict__ fw1, const float* __restrict__ fb1,
    const float* __restrict__ fw2, const float* __restrict__ fb2,
    const float* __restrict__ lng, const float* __restrict__ lnb,
    const float* __restrict__ w2c, const float* __restrict__ b2c,
    const float* __restrict__ w3c, const float* __restrict__ b3c,
    float* __restrict__ outp)
{
  __shared__ __align__(16) float sm[SM_TOT];

  int tid = threadIdx.x;
  int warp = tid>>5, lane = tid&31;
  long base = (long)blockIdx.x * 768;

  for (int idx=tid; idx<768; idx+=256){
    int e = idx/12, t = idx - e*12;
    sm[S_QQ + e*ST+t] = g_out[base+idx] + __ldg(temb + t*64+e);
  }
  __syncthreads();

  for (int l=0; l<LL; l++){
    const float* Wq_  = Wq  + l*4096;
    const float* Wk_  = Wk  + l*4096;
    const float* Wv_  = Wv  + l*4096;
    const float* Wo_  = Wo  + l*4096;
    const float* bo_  = bo  + l*64;
    const float* ln1g_= ln1g+ l*64;  const float* ln1b_= ln1b+ l*64;
    const float* ln2g_= ln2g+ l*64;  const float* ln2b_= ln2b+ l*64;
    const float* fw1_ = fw1 + l*16384; const float* fb1_ = fb1 + l*256;
    const float* fw2_ = fw2 + l*16384; const float* fb2_ = fb2 + l*64;
    const float* lng_ = lng + l*64;  const float* lnb_ = lnb + l*64;

    // ---- Q,K,V split-k: 192 threads = 3 mats x (32 e2 x 2 kgroups) ----
    if (tid < 192){
      int m  = tid >> 6;
      int kg = (tid >> 5) & 1;
      int e2 = tid & 31;
      const float* W = (m==0 ? Wq_ : (m==1 ? Wk_ : Wv_));
      int bi = m*2 + kg;
      float* pb = (bi < 5) ? (sm + S_H + bi*896) : (sm + S_X1);
      u64t A[6]={0,0,0,0,0,0}, B[6]={0,0,0,0,0,0};
      gemm2(sm + S_QQ, W, 64, e2, e2+32, kg*32, 32, A, B);
      store6(pb + e2*PT, A);
      store6(pb + (e2+32)*PT, B);
    }
    __syncthreads();
    // sum partials -> Q,K,V
    for (int idx=tid; idx<2304; idx+=256){
      int m = idx/768, r = idx - m*768;
      int e = r/12, t = r - e*12;
      const float* p0 = (m*2   < 5) ? (sm + S_H + (m*2  )*896) : (sm + S_X1);
      const float* p1 = (m*2+1 < 5) ? (sm + S_H + (m*2+1)*896) : (sm + S_X1);
      float v = p0[e*PT+t] + p1[e*PT+t];
      float* dst = sm + (m==0 ? S_Q : (m==1 ? S_K : S_V));
      dst[e*ST+t] = v;
    }
    __syncthreads();

    // ---- attention scores: 192 threads, 3 scores each ----
    if (tid < 192){
      int h = tid / 48;
      int rem = tid - h*48;
      int t2 = rem >> 2;
      int sq = (rem & 3) * 3;
      const float* qp = sm + S_Q + (h*16)*ST + t2;
      float q[16];
      #pragma unroll
      for (int d=0; d<16; d++) q[d] = qp[d*ST];
      #pragma unroll
      for (int j=0;j<3;j++){
        int s = sq + j;
        const float* kp = sm + S_K + (h*16)*ST + s;
        float sum=0.f;
        #pragma unroll
        for (int d=0;d<16;d++) sum += q[d]*kp[d*ST];
        sm[S_H + (h*12+t2)*12 + s] = sum*0.25f;
      }
    }
    __syncthreads();
    if (tid < 48){
      float* row = sm + S_H + tid*12;
      float mxv = row[0];
      #pragma unroll
      for (int s=1;s<12;s++) mxv = fmaxf(mxv,row[s]);
      float evv[12]; float sum=0.f;
      #pragma unroll
      for (int s=0;s<12;s++){ evv[s]=__expf(row[s]-mxv); sum+=evv[s]; }
      float inv = 1.f/sum;
      #pragma unroll
      for (int s=0;s<12;s++) row[s]=evv[s]*inv;
    }
    __syncthreads();

    // ---- ctx = att @ V (float4 loads; into S_Q) ----
    for (int idx=tid; idx<768; idx+=256){
      int e = idx/12, t2 = idx - e*12, h = e>>4;
      const float4* a4 = (const float4*)(sm + S_H + (h*12+t2)*12);
      const float4* v4 = (const float4*)(sm + S_V + e*ST);
      float4 a0=a4[0], a1=a4[1], a2=a4[2];
      float4 v0=v4[0], v1=v4[1], v2=v4[2];
      float sum = a0.x*v0.x + a0.y*v0.y + a0.z*v0.z + a0.w*v0.w
                + a1.x*v1.x + a1.y*v1.y + a1.z*v1.z + a1.w*v1.w
                + a2.x*v2.x + a2.y*v2.y + a2.z*v2.z + a2.w*v2.w;
      sm[S_Q + e*ST+t2] = sum;
    }
    __syncthreads();

    // ---- attn_out = ctx @ Wo : 128 threads, 4 kgroups; partials -> S_H ----
    if (tid < 128){
      int kg = tid>>5, e2 = tid&31;
      u64t A[6]={0,0,0,0,0,0}, B[6]={0,0,0,0,0,0};
      gemm2(sm + S_Q, Wo_, 64, e2, e2+32, kg*16, 16, A, B);
      float* pb = sm + S_H + kg*896;
      store6(pb + e2*PT, A);
      store6(pb + (e2+32)*PT, B);
    }
    __syncthreads();

    // ---- LN1 merged with Wo-sum + bias + residual; -> S_X1 ----
    for (int t = warp; t < 12; t += 8){
      int e0 = lane, e1 = lane+32;
      float v0 = sm[S_H+e0*PT+t]+sm[S_H+896+e0*PT+t]+sm[S_H+1792+e0*PT+t]+sm[S_H+2688+e0*PT+t]
               + bo_[e0] + sm[S_QQ+e0*ST+t];
      float v1 = sm[S_H+e1*PT+t]+sm[S_H+896+e1*PT+t]+sm[S_H+1792+e1*PT+t]+sm[S_H+2688+e1*PT+t]
               + bo_[e1] + sm[S_QQ+e1*ST+t];
      float s  = warp_sum(v0+v1);
      float s2 = warp_sum(v0*v0+v1*v1);
      float mean = s*(1.f/64.f);
      float var  = s2*(1.f/64.f) - mean*mean;
      float r = rsqrtf(var + 1e-5f);
      sm[S_X1+e0*ST+t] = (v0-mean)*r*ln1g_[e0] + ln1b_[e0];
      sm[S_X1+e1*ST+t] = (v1-mean)*r*ln1g_[e1] + ln1b_[e1];
    }
    __syncthreads();

    // ---- FF1: 128 threads, cols (f, f+128), k=64; relu -> S_H ----
    if (tid < 128){
      int f = tid;
      u64t A[6]={0,0,0,0,0,0}, B[6]={0,0,0,0,0,0};
      gemm2(sm + S_X1, fw1_, 256, f, f+128, 0, 64, A, B);
      float ba = fb1_[f], bb2 = fb1_[f+128];
      float* dA = sm + S_H + f*ST;
      float* dB = sm + S_H + (f+128)*ST;
      #pragma unroll
      for (int p=0;p<6;p++){
        float2 va = *(const float2*)&A[p];
        float2 vb = *(const float2*)&B[p];
        va.x = fmaxf(va.x+ba,0.f);  va.y = fmaxf(va.y+ba,0.f);
        vb.x = fmaxf(vb.x+bb2,0.f); vb.y = fmaxf(vb.y+bb2,0.f);
        ((float2*)dA)[p] = va;
        ((float2*)dB)[p] = vb;
      }
    }
    __syncthreads();

    // ---- FF2: 128 threads, 4 kgroups of 64; partials -> S_Q region ----
    if (tid < 128){
      int kg = tid>>5, e2 = tid&31;
      u64t A[6]={0,0,0,0,0,0}, B[6]={0,0,0,0,0,0};
      gemm2(sm + S_H, fw2_, 64, e2, e2+32, kg*64, 64, A, B);
      float* pb = sm + S_Q + kg*896;
      store6(pb + e2*PT, A);
      store6(pb + (e2+32)*PT, B);
    }
    __syncthreads();

    // ---- LN2 merged with FF2-sum + bias + residual(X1); -> S_X1 ----
    for (int t = warp; t < 12; t += 8){
      int e0 = lane, e1 = lane+32;
      float v0 = sm[S_Q+e0*PT+t]+sm[S_Q+896+e0*PT+t]+sm[S_Q+1792+e0*PT+t]+sm[S_Q+2688+e0*PT+t]
               + fb2_[e0] + sm[S_X1+e0*ST+t];
      float v1 = sm[S_Q+e1*PT+t]+sm[S_Q+896+e1*PT+t]+sm[S_Q+1792+e1*PT+t]+sm[S_Q+2688+e1*PT+t]
               + fb2_[e1] + sm[S_X1+e1*ST+t];
      float s  = warp_sum(v0+v1);
      float s2 = warp_sum(v0*v0+v1*v1);
      float mean = s*(1.f/64.f);
      float var  = s2*(1.f/64.f) - mean*mean;
      float r = rsqrtf(var + 1e-5f);
      sm[S_X1+e0*ST+t] = (v0-mean)*r*ln2g_[e0] + ln2b_[e0];
      sm[S_X1+e1*ST+t] = (v1-mean)*r*ln2g_[e1] + ln2b_[e1];
    }
    __syncthreads();

    // ---- LN3 merged with residual (QQ - temb) ----
    for (int t = warp; t < 12; t += 8){
      int e0 = lane, e1 = lane+32;
      float te0 = __ldg(temb + t*64+e0), te1 = __ldg(temb + t*64+e1);
      float v0 = sm[S_X1+e0*ST+t] + sm[S_QQ+e0*ST+t] - te0;
      float v1 = sm[S_X1+e1*ST+t] + sm[S_QQ+e1*ST+t] - te1;
      float s  = warp_sum(v0+v1);
      float s2 = warp_sum(v0*v0+v1*v1);
      float mean = s*(1.f/64.f);
      float var  = s2*(1.f/64.f) - mean*mean;
      float r = rsqrtf(var + 1e-5f);
      float o0 = (v0-mean)*r*lng_[e0] + lnb_[e0];
      float o1 = (v1-mean)*r*lng_[e1] + lnb_[e1];
      if (l+1 < LL){
        sm[S_QQ+e0*ST+t] = o0 + te0;
        sm[S_QQ+e1*ST+t] = o1 + te1;
      } else {
        sm[S_K+e0*ST+t] = o0;
        sm[S_K+e1*ST+t] = o1;
      }
    }
    __syncthreads();
  }

  // ---- head: conv2 over t (relu) + conv3 over e. out in S_K ----
  if (tid < 192){
    int o = tid>>4, es = (tid&15)*4;
    float w2row[12];
    #pragma unroll
    for (int t=0;t<12;t++) w2row[t] = __ldg(w2c + o*12 + t);
    float b2v = __ldg(b2c + o);
    float acc = 0.f;
    #pragma unroll
    for (int q=0;q<4;q++){
      int e = es + q;
      const float* rowp = sm + S_K + e*ST;
      float v = b2v;
      #pragma unroll
      for (int t=0;t<12;t++) v += rowp[t]*w2row[t];
      v = fmaxf(v, 0.f);
      acc += v * __ldg(w3c + e);
    }
    #pragma unroll
    for (int off=8; off; off>>=1) acc += __shfl_xor_sync(0xffffffffu, acc, off);
    if ((tid&15)==0) outp[(long)blockIdx.x*12 + o] = acc + __ldg(b3c);
  }
}

// ---------------------------------------------------------------------------
extern "C" void kernel_launch(void* const* d_in, const int* in_sizes, int n_in,
                              void* d_out, int out_size) {
  const float* x       = (const float*)d_in[0];
  const int*   adj     = (const int*)  d_in[1];
  const float* gat_W2  = (const float*)d_in[2];
  const float* gat_a   = (const float*)d_in[3];
  const float* gat_b   = (const float*)d_in[4];
  const float* conv1_w = (const float*)d_in[5];
  const float* conv1_b = (const float*)d_in[6];
  const float* temb    = (const float*)d_in[7];
  const float* Wq      = (const float*)d_in[8];
  const float* Wk      = (const float*)d_in[9];
  const float* Wv      = (const float*)d_in[10];
  const float* Wo      = (const float*)d_in[11];
  const float* bo      = (const float*)d_in[12];
  const float* ln1_g   = (const float*)d_in[13];
  const float* ln1_b   = (const float*)d_in[14];
  const float* ln2_g   = (const float*)d_in[15];
  const float* ln2_b   = (const float*)d_in[16];
  const float* ff_w1   = (const float*)d_in[17];
  const float* ff_b1   = (const float*)d_in[18];
  const float* ff_w2   = (const float*)d_in[19];
  const float* ff_b2   = (const float*)d_in[20];
  const float* lng     = (const float*)d_in[21];
  const float* lnb     = (const float*)d_in[22];
  const float* conv2_w = (const float*)d_in[23];
  const float* conv2_b = (const float*)d_in[24];
  const float* conv3_w = (const float*)d_in[25];
  const float* conv3_b = (const float*)d_in[26];
  float* outp = (float*)d_out;

  dim3 g1(BB, (NV + 3) / 4);
  k_gat<<<g1, 256>>>(x, adj, gat_W2, gat_a, gat_b, conv1_w, conv1_b);

  k_fused<<<BB*NV, 256>>>(temb, Wq, Wk, Wv, Wo, bo,
                          ln1_g, ln1_b, ln2_g, ln2_b,
                          ff_w1, ff_b1, ff_w2, ff_b2,
                          lng, lnb,
                          conv2_w, conv2_b, conv3_w, conv3_b, outp);
}

// round 12
// speedup vs baseline: 1.6294x; 1.0926x over previous
#include <cuda_runtime.h>

#define BB 8
#define NV 207
#define TT 12
#define LL 2
#define NGH 8
#define ALPHA 0.2f
#define NN (NV*NV)
#define ST 20   // k-major stride for activation buffers (floats)
#define PT 14   // stride for partial-sum buffers
#define XR 418  // GAT slab row stride (per t)

typedef unsigned long long u64t;

// scratch: gat output (B*N groups, layout per group: e*12+t)
__device__ float g_out[BB*NV*TT*64];

__device__ __forceinline__ float warp_sum(float v){
  #pragma unroll
  for (int o=16;o;o>>=1) v += __shfl_xor_sync(0xffffffffu, v, o);
  return v;
}
__device__ __forceinline__ u64t pack2(float v){
  u64t r; asm("mov.b64 %0, {%1, %1};" : "=l"(r) : "f"(v)); return r;
}
__device__ __forceinline__ void fma2(u64t &acc, u64t a, u64t b){
  asm("fma.rn.f32x2 %0, %1, %2, %0;" : "+l"(acc) : "l"(a), "l"(b));
}

// ---------------------------------------------------------------------------
// K1: GAT + conv1. Block = (b, 2-row chunk), 128 threads (R8 shape).
// x[b] staged TRANSPOSED [t][2n+c]. Closed-form comb indices, hoisted.
// ---------------------------------------------------------------------------
__global__ void __launch_bounds__(128) k_gat(
    const float* __restrict__ x,      // (B,C,N,T)
    const int*   __restrict__ adj,    // (B,N,N)
    const float* __restrict__ W2,     // (8,4,2)
    const float* __restrict__ ga,     // (8,2)
    const float* __restrict__ gb,     // (8,2)
    const float* __restrict__ w1,     // (4,64)
    const float* __restrict__ b1)     // (64)
{
  __shared__ float xsa[TT*XR];     // [t][2n+c]
  __shared__ int   adjs[2*NV];
  __shared__ float w1s[256];
  __shared__ float b1s[64];

  int b  = blockIdx.x;
  int i0 = blockIdx.y * 2;
  int tid = threadIdx.x;

  const float* xb = x + (long)b*2*NV*TT;
  for (int idx=tid; idx<2*NV*TT; idx+=128){
    int c = idx/(NV*TT); int r = idx - c*NV*TT;
    int n = r/TT, t = r - n*TT;
    xsa[t*XR + 2*n + c] = xb[idx];
  }
  int nrows = (NV - i0) < 2 ? (NV - i0) : 2;
  for (int idx=tid; idx<nrows*NV; idx+=128){
    int ii = idx / NV, j = idx - ii*NV;
    adjs[ii*NV+j] = adj[((long)b*NV + i0+ii)*NV + j];
  }
  for (int idx=tid; idx<256; idx+=128) w1s[idx]=w1[idx];
  if (tid<64) b1s[tid]=b1[tid];
  __syncthreads();

  int warp = tid>>5, lane = tid&31;

  for (int task = warp; task < 24; task += 4){
    int t  = task % 12;
    int ii = task / 12;
    int i  = i0 + ii;
    if (i >= NV) continue;
    const int* arow = adjs + ii*NV;
    const float* xrow = xsa + t*XR;

    // ---- pass 1: closed-form comb indices, packed (once per task) ----
    // a0 = (r0<NN)? r0/207 : (r0-NN)%207  with r0=2(i*207+j):
    //   true:  2i + (j>=104);  false: (j>=104)? 2j-207 : 2j
    // a1 (r1=r0+1):
    //   true:  2i + (j>=103);  false: (j>=103)? 2j-206 : 2j+1
    int pk[7];
    #pragma unroll
    for (int jj=0; jj<7; jj++){
      int j = jj*32 + lane;
      bool valid = j < NV;
      int jc = valid ? j : 0;
      bool ok = valid && (arow[jc] > 0);
      int r0 = 2*(i*NV + jc);
      int a0 = (r0   < NN) ? (2*i + (jc>=104)) : ((jc>=104) ? 2*jc-207 : 2*jc);
      int a1 = (r0+1 < NN) ? (2*i + (jc>=103)) : ((jc>=103) ? 2*jc-206 : 2*jc+1);
      pk[jj] = a0 | (a1<<9) | ((ok?1:0)<<18) | (jc<<19);
    }

    float acc0=0.f, acc1=0.f;
    #pragma unroll
    for (int hg=0; hg<2; hg++){
      float w2r[4][4][2], ar[4][2];
      #pragma unroll
      for (int hh=0;hh<4;hh++){
        int h = hg*4+hh;
        #pragma unroll
        for (int k=0;k<4;k++){
          w2r[hh][k][0]=__ldg(W2+(h*4+k)*2+0);
          w2r[hh][k][1]=__ldg(W2+(h*4+k)*2+1);
        }
        ar[hh][0]=__ldg(ga+h*2); ar[hh][1]=__ldg(ga+h*2+1);
      }
      float d[4]={0,0,0,0}, n0[4]={0,0,0,0}, n1[4]={0,0,0,0};
      #pragma unroll
      for (int jj=0; jj<7; jj++){
        int p = pk[jj];
        int a0 =  p        & 511;
        int a1 = (p >> 9)  & 511;
        float okf = (float)((p >> 18) & 1);
        int jc = (p >> 19);
        float2 ca = *(const float2*)(xrow + 2*a0);
        float2 cb = *(const float2*)(xrow + 2*a1);
        float2 xj = *(const float2*)(xrow + 2*jc);
        #pragma unroll
        for (int hh=0;hh<4;hh++){
          float we0 = ca.x*w2r[hh][0][0] + ca.y*w2r[hh][1][0] + cb.x*w2r[hh][2][0] + cb.y*w2r[hh][3][0];
          float we1 = ca.x*w2r[hh][0][1] + ca.y*w2r[hh][1][1] + cb.x*w2r[hh][2][1] + cb.y*w2r[hh][3][1];
          we0 = (we0 > 0.f) ? we0 : ALPHA*we0;
          we1 = (we1 > 0.f) ? we1 : ALPHA*we1;
          float e = we0*ar[hh][0] + we1*ar[hh][1];
          float w = okf * __expf(e);
          d[hh]  += w;
          n0[hh] += w*xj.x;
          n1[hh] += w*xj.y;
        }
      }
      #pragma unroll
      for (int off=16; off; off>>=1){
        #pragma unroll
        for (int hh=0;hh<4;hh++){
          d[hh]  += __shfl_xor_sync(0xffffffffu, d[hh],  off);
          n0[hh] += __shfl_xor_sync(0xffffffffu, n0[hh], off);
          n1[hh] += __shfl_xor_sync(0xffffffffu, n1[hh], off);
        }
      }
      #pragma unroll
      for (int hh=0;hh<4;hh++){
        int h = hg*4+hh;
        float inv = 1.0f/d[hh];
        float z0 = n0[hh]*inv + __ldg(gb+h*2+0);
        float z1 = n1[hh]*inv + __ldg(gb+h*2+1);
        acc0 += 1.f - __fdividef(2.f, __expf(2.f*z0)+1.f);
        acc1 += 1.f - __fdividef(2.f, __expf(2.f*z1)+1.f);
      }
    }
    acc0 *= 0.125f; acc1 *= 0.125f;

    float xi0 = xrow[2*i], xi1 = xrow[2*i+1];
    long obase = (long)(b*NV + i)*768;
    #pragma unroll
    for (int r=0;r<2;r++){
      int e = lane + r*32;
      g_out[obase + e*12 + t] = xi0*w1s[e] + xi1*w1s[64+e]
                              + acc0*w1s[128+e] + acc1*w1s[192+e] + b1s[e];
    }
  }
}

// ---------------------------------------------------------------------------
// 2-column GEMM (R8 version: per-lane coalesced weight LDG).
// ---------------------------------------------------------------------------
__device__ __forceinline__ void gemm2(const float* __restrict__ sIn,
                                      const float* __restrict__ W, int ldw,
                                      int c0, int c1, int k0, int nk,
                                      u64t A[6], u64t Bc[6]){
  #pragma unroll 4
  for (int k=k0; k<k0+nk; k++){
    const float* wr = W + (long)k*ldw;
    u64t wa = pack2(__ldg(wr+c0));
    u64t wb = pack2(__ldg(wr+c1));
    const ulonglong2* a = (const ulonglong2*)(sIn + k*ST);
    ulonglong2 v0 = a[0], v1 = a[1], v2 = a[2];
    fma2(A[0], v0.x, wa); fma2(Bc[0], v0.x, wb);
    fma2(A[1], v0.y, wa); fma2(Bc[1], v0.y, wb);
    fma2(A[2], v1.x, wa); fma2(Bc[2], v1.x, wb);
    fma2(A[3], v1.y, wa); fma2(Bc[3], v1.y, wb);
    fma2(A[4], v2.x, wa); fma2(Bc[4], v2.x, wb);
    fma2(A[5], v2.y, wa); fma2(Bc[5], v2.y, wb);
  }
}

__device__ __forceinline__ void store6(float* dst, const u64t A[6]){
  #pragma unroll
  for (int p=0;p<6;p++) ((float2*)dst)[p] = *(const float2*)&A[p];
}

// ---------------------------------------------------------------------------
// K2: BOTH transformer layers + conv2/conv3 head fused (exact R8 body).
// grid 1656 (=B*N), block 256. smem arena 46KB.
// ---------------------------------------------------------------------------
#define S_QQ 0
#define S_Q  1280
#define S_K  2560
#define S_V  3840
#define S_X1 5120
#define S_H  6400      // 5120 floats
#define SM_TOT 11520

__global__ void __launch_bounds__(256, 4) k_fused(
    const float* __restrict__ temb,
    const float* __restrict__ Wq, const float* __restrict__ Wk,
    const float* __restrict__ Wv, const float* __restrict__ Wo,
    const float* __restrict__ bo,
    const float* __restrict__ ln1g, const float* __restrict__ ln1b,
    const float* __restrict__ ln2g, const float* __restrict__ ln2b,
    const float* __restrict__ fw1, const float* __restrict__ fb1,
    const float* __restrict__ fw2, const float* __restrict__ fb2,
    const float* __restrict__ lng, const float* __restrict__ lnb,
    const float* __restrict__ w2c, const float* __restrict__ b2c,
    const float* __restrict__ w3c, const float* __restrict__ b3c,
    float* __restrict__ outp)
{
  __shared__ __align__(16) float sm[SM_TOT];

  int tid = threadIdx.x;
  int warp = tid>>5, lane = tid&31;
  long base = (long)blockIdx.x * 768;

  for (int idx=tid; idx<768; idx+=256){
    int e = idx/12, t = idx - e*12;
    sm[S_QQ + e*ST+t] = g_out[base+idx] + __ldg(temb + t*64+e);
  }
  __syncthreads();

  for (int l=0; l<LL; l++){
    const float* Wq_  = Wq  + l*4096;
    const float* Wk_  = Wk  + l*4096;
    const float* Wv_  = Wv  + l*4096;
    const float* Wo_  = Wo  + l*4096;
    const float* bo_  = bo  + l*64;
    const float* ln1g_= ln1g+ l*64;  const float* ln1b_= ln1b+ l*64;
    const float* ln2g_= ln2g+ l*64;  const float* ln2b_= ln2b+ l*64;
    const float* fw1_ = fw1 + l*16384; const float* fb1_ = fb1 + l*256;
    const float* fw2_ = fw2 + l*16384; const float* fb2_ = fb2 + l*64;
    const float* lng_ = lng + l*64;  const float* lnb_ = lnb + l*64;

    // ---- Q,K,V split-k: 192 threads = 3 mats x (32 e2 x 2 kgroups) ----
    if (tid < 192){
      int m  = tid >> 6;
      int kg = (tid >> 5) & 1;
      int e2 = tid & 31;
      const float* W = (m==0 ? Wq_ : (m==1 ? Wk_ : Wv_));
      int bi = m*2 + kg;
      float* pb = (bi < 5) ? (sm + S_H + bi*896) : (sm + S_X1);
      u64t A[6]={0,0,0,0,0,0}, B[6]={0,0,0,0,0,0};
      gemm2(sm + S_QQ, W, 64, e2, e2+32, kg*32, 32, A, B);
      store6(pb + e2*PT, A);
      store6(pb + (e2+32)*PT, B);
    }
    __syncthreads();
    // sum partials -> Q,K,V
    for (int idx=tid; idx<2304; idx+=256){
      int m = idx/768, r = idx - m*768;
      int e = r/12, t = r - e*12;
      const float* p0 = (m*2   < 5) ? (sm + S_H + (m*2  )*896) : (sm + S_X1);
      const float* p1 = (m*2+1 < 5) ? (sm + S_H + (m*2+1)*896) : (sm + S_X1);
      float v = p0[e*PT+t] + p1[e*PT+t];
      float* dst = sm + (m==0 ? S_Q : (m==1 ? S_K : S_V));
      dst[e*ST+t] = v;
    }
    __syncthreads();

    // ---- attention scores: 192 threads, 3 scores each ----
    if (tid < 192){
      int h = tid / 48;
      int rem = tid - h*48;
      int t2 = rem >> 2;
      int sq = (rem & 3) * 3;
      const float* qp = sm + S_Q + (h*16)*ST + t2;
      float q[16];
      #pragma unroll
      for (int d=0; d<16; d++) q[d] = qp[d*ST];
      #pragma unroll
      for (int j=0;j<3;j++){
        int s = sq + j;
        const float* kp = sm + S_K + (h*16)*ST + s;
        float sum=0.f;
        #pragma unroll
        for (int d=0;d<16;d++) sum += q[d]*kp[d*ST];
        sm[S_H + (h*12+t2)*12 + s] = sum*0.25f;
      }
    }
    __syncthreads();
    if (tid < 48){
      float* row = sm + S_H + tid*12;
      float mxv = row[0];
      #pragma unroll
      for (int s=1;s<12;s++) mxv = fmaxf(mxv,row[s]);
      float evv[12]; float sum=0.f;
      #pragma unroll
      for (int s=0;s<12;s++){ evv[s]=__expf(row[s]-mxv); sum+=evv[s]; }
      float inv = 1.f/sum;
      #pragma unroll
      for (int s=0;s<12;s++) row[s]=evv[s]*inv;
    }
    __syncthreads();

    // ---- ctx = att @ V (float4 loads; into S_Q) ----
    for (int idx=tid; idx<768; idx+=256){
      int e = idx/12, t2 = idx - e*12, h = e>>4;
      const float4* a4 = (const float4*)(sm + S_H + (h*12+t2)*12);
      const float4* v4 = (const float4*)(sm + S_V + e*ST);
      float4 a0=a4[0], a1=a4[1], a2=a4[2];
      float4 v0=v4[0], v1=v4[1], v2=v4[2];
      float sum = a0.x*v0.x + a0.y*v0.y + a0.z*v0.z + a0.w*v0.w
                + a1.x*v1.x + a1.y*v1.y + a1.z*v1.z + a1.w*v1.w
                + a2.x*v2.x + a2.y*v2.y + a2.z*v2.z + a2.w*v2.w;
      sm[S_Q + e*ST+t2] = sum;
    }
    __syncthreads();

    // ---- attn_out = ctx @ Wo : 128 threads, 4 kgroups; partials -> S_H ----
    if (tid < 128){
      int kg = tid>>5, e2 = tid&31;
      u64t A[6]={0,0,0,0,0,0}, B[6]={0,0,0,0,0,0};
      gemm2(sm + S_Q, Wo_, 64, e2, e2+32, kg*16, 16, A, B);
      float* pb = sm + S_H + kg*896;
      store6(pb + e2*PT, A);
      store6(pb + (e2+32)*PT, B);
    }
    __syncthreads();

    // ---- LN1 merged with Wo-sum + bias + residual; -> S_X1 ----
    for (int t = warp; t < 12; t += 8){
      int e0 = lane, e1 = lane+32;
      float v0 = sm[S_H+e0*PT+t]+sm[S_H+896+e0*PT+t]+sm[S_H+1792+e0*PT+t]+sm[S_H+2688+e0*PT+t]
               + bo_[e0] + sm[S_QQ+e0*ST+t];
      float v1 = sm[S_H+e1*PT+t]+sm[S_H+896+e1*PT+t]+sm[S_H+1792+e1*PT+t]+sm[S_H+2688+e1*PT+t]
               + bo_[e1] + sm[S_QQ+e1*ST+t];
      float s  = warp_sum(v0+v1);
      float s2 = warp_sum(v0*v0+v1*v1);
      float mean = s*(1.f/64.f);
      float var  = s2*(1.f/64.f) - mean*mean;
      float r = rsqrtf(var + 1e-5f);
      sm[S_X1+e0*ST+t] = (v0-mean)*r*ln1g_[e0] + ln1b_[e0];
      sm[S_X1+e1*ST+t] = (v1-mean)*r*ln1g_[e1] + ln1b_[e1];
    }
    __syncthreads();

    // ---- FF1: 128 threads, cols (f, f+128), k=64; relu -> S_H ----
    if (tid < 128){
      int f = tid;
      u64t A[6]={0,0,0,0,0,0}, B[6]={0,0,0,0,0,0};
      gemm2(sm + S_X1, fw1_, 256, f, f+128, 0, 64, A, B);
      float ba = fb1_[f], bb2 = fb1_[f+128];
      float* dA = sm + S_H + f*ST;
      float* dB = sm + S_H + (f+128)*ST;
      #pragma unroll
      for (int p=0;p<6;p++){
        float2 va = *(const float2*)&A[p];
        float2 vb = *(const float2*)&B[p];
        va.x = fmaxf(va.x+ba,0.f);  va.y = fmaxf(va.y+ba,0.f);
        vb.x = fmaxf(vb.x+bb2,0.f); vb.y = fmaxf(vb.y+bb2,0.f);
        ((float2*)dA)[p] = va;
        ((float2*)dB)[p] = vb;
      }
    }
    __syncthreads();

    // ---- FF2: 128 threads, 4 kgroups of 64; partials -> S_Q region ----
    if (tid < 128){
      int kg = tid>>5, e2 = tid&31;
      u64t A[6]={0,0,0,0,0,0}, B[6]={0,0,0,0,0,0};
      gemm2(sm + S_H, fw2_, 64, e2, e2+32, kg*64, 64, A, B);
      float* pb = sm + S_Q + kg*896;
      store6(pb + e2*PT, A);
      store6(pb + (e2+32)*PT, B);
    }
    __syncthreads();

    // ---- LN2 merged with FF2-sum + bias + residual(X1); -> S_X1 ----
    for (int t = warp; t < 12; t += 8){
      int e0 = lane, e1 = lane+32;
      float v0 = sm[S_Q+e0*PT+t]+sm[S_Q+896+e0*PT+t]+sm[S_Q+1792+e0*PT+t]+sm[S_Q+2688+e0*PT+t]
               + fb2_[e0] + sm[S_X1+e0*ST+t];
      float v1 = sm[S_Q+e1*PT+t]+sm[S_Q+896+e1*PT+t]+sm[S_Q+1792+e1*PT+t]+sm[S_Q+2688+e1*PT+t]
               + fb2_[e1] + sm[S_X1+e1*ST+t];
      float s  = warp_sum(v0+v1);
      float s2 = warp_sum(v0*v0+v1*v1);
      float mean = s*(1.f/64.f);
      float var  = s2*(1.f/64.f) - mean*mean;
      float r = rsqrtf(var + 1e-5f);
      sm[S_X1+e0*ST+t] = (v0-mean)*r*ln2g_[e0] + ln2b_[e0];
      sm[S_X1+e1*ST+t] = (v1-mean)*r*ln2g_[e1] + ln2b_[e1];
    }
    __syncthreads();

    // ---- LN3 merged with residual (QQ - temb) ----
    for (int t = warp; t < 12; t += 8){
      int e0 = lane, e1 = lane+32;
      float te0 = __ldg(temb + t*64+e0), te1 = __ldg(temb + t*64+e1);
      float v0 = sm[S_X1+e0*ST+t] + sm[S_QQ+e0*ST+t] - te0;
      float v1 = sm[S_X1+e1*ST+t] + sm[S_QQ+e1*ST+t] - te1;
      float s  = warp_sum(v0+v1);
      float s2 = warp_sum(v0*v0+v1*v1);
      float mean = s*(1.f/64.f);
      float var  = s2*(1.f/64.f) - mean*mean;
      float r = rsqrtf(var + 1e-5f);
      float o0 = (v0-mean)*r*lng_[e0] + lnb_[e0];
      float o1 = (v1-mean)*r*lng_[e1] + lnb_[e1];
      if (l+1 < LL){
        sm[S_QQ+e0*ST+t] = o0 + te0;
        sm[S_QQ+e1*ST+t] = o1 + te1;
      } else {
        sm[S_K+e0*ST+t] = o0;
        sm[S_K+e1*ST+t] = o1;
      }
    }
    __syncthreads();
  }

  // ---- head: conv2 over t (relu) + conv3 over e. out in S_K ----
  if (tid < 192){
    int o = tid>>4, es = (tid&15)*4;
    float w2row[12];
    #pragma unroll
    for (int t=0;t<12;t++) w2row[t] = __ldg(w2c + o*12 + t);
    float b2v = __ldg(b2c + o);
    float acc = 0.f;
    #pragma unroll
    for (int q=0;q<4;q++){
      int e = es + q;
      const float* rowp = sm + S_K + e*ST;
      float v = b2v;
      #pragma unroll
      for (int t=0;t<12;t++) v += rowp[t]*w2row[t];
      v = fmaxf(v, 0.f);
      acc += v * __ldg(w3c + e);
    }
    #pragma unroll
    for (int off=8; off; off>>=1) acc += __shfl_xor_sync(0xffffffffu, acc, off);
    if ((tid&15)==0) outp[(long)blockIdx.x*12 + o] = acc + __ldg(b3c);
  }
}

// ---------------------------------------------------------------------------
extern "C" void kernel_launch(void* const* d_in, const int* in_sizes, int n_in,
                              void* d_out, int out_size) {
  const float* x       = (const float*)d_in[0];
  const int*   adj     = (const int*)  d_in[1];
  const float* gat_W2  = (const float*)d_in[2];
  const float* gat_a   = (const float*)d_in[3];
  const float* gat_b   = (const float*)d_in[4];
  const float* conv1_w = (const float*)d_in[5];
  const float* conv1_b = (const float*)d_in[6];
  const float* temb    = (const float*)d_in[7];
  const float* Wq      = (const float*)d_in[8];
  const float* Wk      = (const float*)d_in[9];
  const float* Wv      = (const float*)d_in[10];
  const float* Wo      = (const float*)d_in[11];
  const float* bo      = (const float*)d_in[12];
  const float* ln1_g   = (const float*)d_in[13];
  const float* ln1_b   = (const float*)d_in[14];
  const float* ln2_g   = (const float*)d_in[15];
  const float* ln2_b   = (const float*)d_in[16];
  const float* ff_w1   = (const float*)d_in[17];
  const float* ff_b1   = (const float*)d_in[18];
  const float* ff_w2   = (const float*)d_in[19];
  const float* ff_b2   = (const float*)d_in[20];
  const float* lng     = (const float*)d_in[21];
  const float* lnb     = (const float*)d_in[22];
  const float* conv2_w = (const float*)d_in[23];
  const float* conv2_b = (const float*)d_in[24];
  const float* conv3_w = (const float*)d_in[25];
  const float* conv3_b = (const float*)d_in[26];
  float* outp = (float*)d_out;

  dim3 g1(BB, (NV + 1) / 2);
  k_gat<<<g1, 128>>>(x, adj, gat_W2, gat_a, gat_b, conv1_w, conv1_b);

  k_fused<<<BB*NV, 256>>>(temb, Wq, Wk, Wv, Wo, bo,
                          ln1_g, ln1_b, ln2_g, ln2_b,
                          ff_w1, ff_b1, ff_w2, ff_b2,
                          lng, lnb,
                          conv2_w, conv2_b, conv3_w, conv3_b, outp);
}